// round 8
// baseline (speedup 1.0000x reference)
#include <cuda_runtime.h>
#include <math.h>
#include <stdint.h>

// Problem constants
#define B_   8
#define C_   256
#define N_   4096
#define CQ   32

// ---------------- scratch (static device arrays; no allocation) -------------
__device__ float g_Q[(size_t)B_ * N_ * CQ];   // [b][n][d]  4 MB
__device__ float g_K[(size_t)B_ * N_ * CQ];   // [b][n][d]  4 MB (K transposed)
__device__ float g_V[(size_t)B_ * N_ * C_];   // [b][n][c] 32 MB (V transposed)

// ---------------- f32x2 packed math helpers (sm_103a) -----------------------
__device__ __forceinline__ unsigned long long pack2(float x, float y) {
    unsigned long long r;
    asm("mov.b64 %0, {%1, %2};" : "=l"(r) : "f"(x), "f"(y));
    return r;
}
__device__ __forceinline__ float2 unpack2(unsigned long long v) {
    float2 r;
    asm("mov.b64 {%0, %1}, %2;" : "=f"(r.x), "=f"(r.y) : "l"(v));
    return r;
}
__device__ __forceinline__ void fma2(unsigned long long& d,
                                     unsigned long long a, unsigned long long b) {
    asm("fma.rn.f32x2 %0, %1, %2, %0;" : "+l"(d) : "l"(a), "l"(b));
}
__device__ __forceinline__ unsigned long long mul2(unsigned long long a,
                                                   unsigned long long b) {
    unsigned long long d;
    asm("mul.rn.f32x2 %0, %1, %2;" : "=l"(d) : "l"(a), "l"(b));
    return d;
}

// 16-lane (half-warp) reductions; tx = lane&15 threads share a row group
__device__ __forceinline__ float red_max16(float v) {
#pragma unroll
    for (int off = 8; off; off >>= 1)
        v = fmaxf(v, __shfl_xor_sync(0xffffffffu, v, off));
    return v;
}
__device__ __forceinline__ float red_sum16(float v) {
#pragma unroll
    for (int off = 8; off; off >>= 1)
        v += __shfl_xor_sync(0xffffffffu, v, off);
    return v;
}

// ============================================================================
// Kernel 1: fused Q/K/V projection (1x1 conv == channel GEMM)
//   out320[n][o] = sum_c x[b][c][n] * Wcat[o][c] + bcat[o]
//   o in [0,32)  -> Q[b][n][o]
//   o in [32,64) -> K[b][n][o-32]
//   o in [64,320)-> V[b][n][o-64]
// grid: (N/128, 320/64, B), block: 256
// ============================================================================
__global__ __launch_bounds__(256)
void proj_kernel(const float* __restrict__ x,
                 const float* __restrict__ wq, const float* __restrict__ bq,
                 const float* __restrict__ wk, const float* __restrict__ bk,
                 const float* __restrict__ wv, const float* __restrict__ bv)
{
    __shared__ __align__(16) float xs[32][128];   // [c][n] tile
    __shared__ float ws[64][33];                  // [o][c] tile, padded

    const int b  = blockIdx.z;
    const int n0 = blockIdx.x * 128;
    const int o0 = blockIdx.y * 64;
    const int t  = threadIdx.x;
    const int txo = t & 15;        // o group: 4 outputs each
    const int tyn = t >> 4;        // n group: 8 n each

    unsigned long long acc[4][4];  // [o][n-pair], f32x2 along n
#pragma unroll
    for (int k = 0; k < 4; k++)
#pragma unroll
        for (int p = 0; p < 4; p++) acc[k][p] = 0ULL;

    const float* xb = x + (size_t)b * C_ * N_;

    for (int c0 = 0; c0 < C_; c0 += 32) {
        // load x tile [32 c][128 n], coalesced float4
#pragma unroll
        for (int r = 0; r < 4; r++) {
            int idx = t + r * 256;          // vec4 id, 0..1023
            int cc  = idx >> 5;
            int nn  = (idx & 31) * 4;
            *(float4*)&xs[cc][nn] =
                *(const float4*)&xb[(size_t)(c0 + cc) * N_ + n0 + nn];
        }
        // load W tile [64 o][32 c], scalar (padded smem)
#pragma unroll
        for (int r = 0; r < 8; r++) {
            int idx = t + r * 256;          // 0..2047
            int oo  = idx >> 5;
            int cc  = idx & 31;
            int og  = o0 + oo;
            const float* wrow = (og < 32) ? (wq + (size_t)og * C_)
                              : (og < 64) ? (wk + (size_t)(og - 32) * C_)
                                          : (wv + (size_t)(og - 64) * C_);
            ws[oo][cc] = wrow[c0 + cc];
        }
        __syncthreads();

#pragma unroll 8
        for (int cc = 0; cc < 32; cc++) {
            float4 a0 = *(float4*)&xs[cc][tyn * 8];
            float4 a1 = *(float4*)&xs[cc][tyn * 8 + 4];
            unsigned long long av[4] = { pack2(a0.x, a0.y), pack2(a0.z, a0.w),
                                         pack2(a1.x, a1.y), pack2(a1.z, a1.w) };
#pragma unroll
            for (int k = 0; k < 4; k++) {
                float w = ws[txo * 4 + k][cc];
                unsigned long long w2 = pack2(w, w);
#pragma unroll
                for (int p = 0; p < 4; p++) fma2(acc[k][p], w2, av[p]);
            }
        }
        __syncthreads();
    }

    // epilogue: bias + scatter to Q/K/V scratch
#pragma unroll
    for (int k = 0; k < 4; k++) {
        int og = o0 + txo * 4 + k;
        float bias;
        float* dst;
        int S, ol;
        if (og < 32)       { bias = bq[og];      dst = g_Q; S = CQ; ol = og; }
        else if (og < 64)  { bias = bk[og - 32]; dst = g_K; S = CQ; ol = og - 32; }
        else               { bias = bv[og - 64]; dst = g_V; S = C_; ol = og - 64; }
#pragma unroll
        for (int p = 0; p < 4; p++) {
            float2 v = unpack2(acc[k][p]);
            int n = n0 + tyn * 8 + p * 2;
            dst[((size_t)b * N_ + n    ) * S + ol] = v.x + bias;
            dst[((size_t)b * N_ + n + 1) * S + ol] = v.y + bias;
        }
    }
}

// ============================================================================
// Kernel 2: flash attention (no scale, softmax over keys) + residual
//   O[i][c] = sum_j softmax_j(Q[i]·K[j]) * V[j][c];  out = x + O^T
// grid: (N/128, C/128, B), block: 256, dyn smem 164864 B
// Thread map: tx = t&15, ti = t>>4.
//   Phase 1 (S):  rows i = ti*8..+8, keys j = tx + 16*jj (strided, bank-safe)
//   Phase 2 (PV): rows i = ti*8..+8, chans c = tx*8..+8 (f32x2 pairs along c)
// ============================================================================
#define BM 128
#define BN 128
#define BC 128

__global__ __launch_bounds__(256)
void attn_kernel(const float* __restrict__ x, float* __restrict__ out)
{
    extern __shared__ __align__(16) float sm[];
    float* sQ = sm;                       // [128][33]
    float* sK = sQ + 128 * 33;            // [128][33]
    float* sV = sK + 128 * 33;            // [128][128]  [j][c]
    float* sP = sV + 128 * 128;           // [128][128]  [i][j], later [c][i]

    const int b  = blockIdx.z;
    const int i0 = blockIdx.x * BM;
    const int c0 = blockIdx.y * BC;
    const int t  = threadIdx.x;
    const int tx = t & 15;
    const int ti = t >> 4;

    const float* Qg = g_Q + ((size_t)b * N_ + i0) * CQ;

    // load Q tile [128 i][32 d] -> sQ (padded rows)
#pragma unroll
    for (int r = 0; r < 4; r++) {
        int idx = t + r * 256;          // vec4 id
        int ii  = idx >> 3;
        int dd  = (idx & 7) * 4;
        float4 v = *(const float4*)&Qg[(size_t)ii * CQ + dd];
        float* d = &sQ[ii * 33 + dd];
        d[0] = v.x; d[1] = v.y; d[2] = v.z; d[3] = v.w;
    }

    float m[8], l[8];
    unsigned long long O2[8][4];
#pragma unroll
    for (int ii = 0; ii < 8; ii++) {
        m[ii] = -3.0e38f; l[ii] = 0.0f;
#pragma unroll
        for (int p = 0; p < 4; p++) O2[ii][p] = 0ULL;
    }

    for (int j0 = 0; j0 < N_; j0 += BN) {
        // ---- load K tile [128 j][32 d] and V tile [128 j][128 c] ----
        const float* Kg = g_K + ((size_t)b * N_ + j0) * CQ;
#pragma unroll
        for (int r = 0; r < 4; r++) {
            int idx = t + r * 256;
            int jj  = idx >> 3;
            int dd  = (idx & 7) * 4;
            float4 v = *(const float4*)&Kg[(size_t)jj * CQ + dd];
            float* d = &sK[jj * 33 + dd];
            d[0] = v.x; d[1] = v.y; d[2] = v.z; d[3] = v.w;
        }
#pragma unroll
        for (int r = 0; r < 16; r++) {
            int idx = t + r * 256;          // vec4 id, 0..4095
            int jj  = idx >> 5;
            int cc  = (idx & 31) * 4;
            *(float4*)&sV[jj * 128 + cc] =
                *(const float4*)&g_V[((size_t)b * N_ + j0 + jj) * C_ + c0 + cc];
        }
        __syncthreads();

        // ---- phase 1: S = Q K^T (8 i x 8 j per thread, scalar fp32) ----
        float s[8][8];
#pragma unroll
        for (int ii = 0; ii < 8; ii++)
#pragma unroll
            for (int jj = 0; jj < 8; jj++) s[ii][jj] = 0.0f;

#pragma unroll 8
        for (int d = 0; d < CQ; d++) {
            float q[8], k[8];
#pragma unroll
            for (int ii = 0; ii < 8; ii++) q[ii] = sQ[(ti * 8 + ii) * 33 + d];
#pragma unroll
            for (int jj = 0; jj < 8; jj++) k[jj] = sK[(tx + jj * 16) * 33 + d];
#pragma unroll
            for (int ii = 0; ii < 8; ii++)
#pragma unroll
                for (int jj = 0; jj < 8; jj++) s[ii][jj] += q[ii] * k[jj];
        }

        // ---- online softmax ----
        float f[8];
#pragma unroll
        for (int ii = 0; ii < 8; ii++) {
            float v = s[ii][0];
#pragma unroll
            for (int jj = 1; jj < 8; jj++) v = fmaxf(v, s[ii][jj]);
            v = red_max16(v);
            float mnew = fmaxf(m[ii], v);
            f[ii] = __expf(m[ii] - mnew);
            m[ii] = mnew;

            float rs = 0.0f;
#pragma unroll
            for (int jj = 0; jj < 8; jj++) {
                float p = __expf(s[ii][jj] - mnew);
                s[ii][jj] = p;
                rs += p;
            }
            rs = red_sum16(rs);
            l[ii] = l[ii] * f[ii] + rs;
        }
        // rescale O (f32x2)
#pragma unroll
        for (int ii = 0; ii < 8; ii++) {
            unsigned long long f2 = pack2(f[ii], f[ii]);
#pragma unroll
            for (int p = 0; p < 4; p++) O2[ii][p] = mul2(O2[ii][p], f2);
        }
        // write P -> sP[i][j]  (j = tx + 16*jj: conflict-free scalar stores)
#pragma unroll
        for (int ii = 0; ii < 8; ii++)
#pragma unroll
            for (int jj = 0; jj < 8; jj++)
                sP[(ti * 8 + ii) * 128 + tx + jj * 16] = s[ii][jj];
        __syncthreads();

        // ---- phase 2: O += P V  (f32x2 pairs along c) ----
#pragma unroll 2
        for (int j = 0; j < BN; j++) {
            float4 va = *(float4*)&sV[j * 128 + tx * 8];
            float4 vb = *(float4*)&sV[j * 128 + tx * 8 + 4];
            unsigned long long v2[4] = { pack2(va.x, va.y), pack2(va.z, va.w),
                                         pack2(vb.x, vb.y), pack2(vb.z, vb.w) };
#pragma unroll
            for (int ii = 0; ii < 8; ii++) {
                float p = sP[(ti * 8 + ii) * 128 + j];   // broadcast
                unsigned long long p2 = pack2(p, p);
                fma2(O2[ii][0], p2, v2[0]);
                fma2(O2[ii][1], p2, v2[1]);
                fma2(O2[ii][2], p2, v2[2]);
                fma2(O2[ii][3], p2, v2[3]);
            }
        }
        __syncthreads();
    }

    // ---- epilogue: normalize, transpose via smem, residual add, store ----
#pragma unroll
    for (int ii = 0; ii < 8; ii++) {
        float inv = 1.0f / l[ii];
#pragma unroll
        for (int p = 0; p < 4; p++) {
            float2 v = unpack2(O2[ii][p]);
            int cl = tx * 8 + p * 2;
            sP[(cl    ) * 128 + ti * 8 + ii] = v.x * inv;   // sO[c][i]
            sP[(cl + 1) * 128 + ti * 8 + ii] = v.y * inv;
        }
    }
    __syncthreads();

    const float* xb = x   + ((size_t)b * C_ + c0) * N_ + i0;
    float*       ob = out + ((size_t)b * C_ + c0) * N_ + i0;
#pragma unroll
    for (int r = 0; r < 16; r++) {
        int idx = t + r * 256;          // vec4 id, 0..4095
        int cc  = idx >> 5;
        int iv  = (idx & 31) * 4;
        float4 o4 = *(float4*)&sP[cc * 128 + iv];
        float4 xv = *(const float4*)&xb[(size_t)cc * N_ + iv];
        o4.x += xv.x; o4.y += xv.y; o4.z += xv.z; o4.w += xv.w;
        *(float4*)&ob[(size_t)cc * N_ + iv] = o4;
    }
}

// ============================================================================
extern "C" void kernel_launch(void* const* d_in, const int* in_sizes, int n_in,
                              void* d_out, int out_size)
{
    const float* x  = (const float*)d_in[0];
    const float* wq = (const float*)d_in[1];
    const float* bq = (const float*)d_in[2];
    const float* wk = (const float*)d_in[3];
    const float* bk = (const float*)d_in[4];
    const float* wv = (const float*)d_in[5];
    const float* bv = (const float*)d_in[6];
    float* out = (float*)d_out;

    // projections: Q,K -> [B,N,32]; V^T -> [B,N,256]
    proj_kernel<<<dim3(N_ / 128, 320 / 64, B_), 256>>>(x, wq, bq, wk, bk, wv, bv);

    // flash attention + residual
    const int smem = (2 * 128 * 33 + 2 * 128 * 128) * (int)sizeof(float); // 164864
    cudaFuncSetAttribute(attn_kernel,
                         cudaFuncAttributeMaxDynamicSharedMemorySize, smem);
    attn_kernel<<<dim3(N_ / BM, C_ / BC, B_), 256, smem>>>(x, out);
}

// round 9
// speedup vs baseline: 1.0006x; 1.0006x over previous
#include <cuda_runtime.h>
#include <math.h>
#include <stdint.h>

// Problem constants
#define B_   8
#define C_   256
#define N_   4096
#define CQ   32

// ---------------- scratch (static device arrays; no allocation) -------------
__device__ float g_Q[(size_t)B_ * N_ * CQ];   // [b][n][d]  4 MB
__device__ float g_K[(size_t)B_ * N_ * CQ];   // [b][n][d]  4 MB (K transposed)
__device__ float g_V[(size_t)B_ * N_ * C_];   // [b][n][c] 32 MB (V transposed)

// ---------------- f32x2 packed math helpers (sm_103a) -----------------------
__device__ __forceinline__ unsigned long long pack2(float x, float y) {
    unsigned long long r;
    asm("mov.b64 %0, {%1, %2};" : "=l"(r) : "f"(x), "f"(y));
    return r;
}
__device__ __forceinline__ float2 unpack2(unsigned long long v) {
    float2 r;
    asm("mov.b64 {%0, %1}, %2;" : "=f"(r.x), "=f"(r.y) : "l"(v));
    return r;
}
__device__ __forceinline__ void fma2(unsigned long long& d,
                                     unsigned long long a, unsigned long long b) {
    asm("fma.rn.f32x2 %0, %1, %2, %0;" : "+l"(d) : "l"(a), "l"(b));
}
__device__ __forceinline__ unsigned long long mul2(unsigned long long a,
                                                   unsigned long long b) {
    unsigned long long d;
    asm("mul.rn.f32x2 %0, %1, %2;" : "=l"(d) : "l"(a), "l"(b));
    return d;
}

// 16-lane (half-warp) reductions; tx = lane&15 threads share a row group
__device__ __forceinline__ float red_max16(float v) {
#pragma unroll
    for (int off = 8; off; off >>= 1)
        v = fmaxf(v, __shfl_xor_sync(0xffffffffu, v, off));
    return v;
}
__device__ __forceinline__ float red_sum16(float v) {
#pragma unroll
    for (int off = 8; off; off >>= 1)
        v += __shfl_xor_sync(0xffffffffu, v, off);
    return v;
}

// ============================================================================
// Kernel 1: fused Q/K/V projection (1x1 conv == channel GEMM)
//   out320[n][o] = sum_c x[b][c][n] * Wcat[o][c] + bcat[o]
//   o in [0,32)  -> Q[b][n][o]
//   o in [32,64) -> K[b][n][o-32]
//   o in [64,320)-> V[b][n][o-64]
// grid: (N/128, 320/64, B), block: 256
// ============================================================================
__global__ __launch_bounds__(256)
void proj_kernel(const float* __restrict__ x,
                 const float* __restrict__ wq, const float* __restrict__ bq,
                 const float* __restrict__ wk, const float* __restrict__ bk,
                 const float* __restrict__ wv, const float* __restrict__ bv)
{
    __shared__ __align__(16) float xs[32][128];   // [c][n] tile
    __shared__ float ws[64][33];                  // [o][c] tile, padded

    const int b  = blockIdx.z;
    const int n0 = blockIdx.x * 128;
    const int o0 = blockIdx.y * 64;
    const int t  = threadIdx.x;
    const int txo = t & 15;        // o group: 4 outputs each
    const int tyn = t >> 4;        // n group: 8 n each

    unsigned long long acc[4][4];  // [o][n-pair], f32x2 along n
#pragma unroll
    for (int k = 0; k < 4; k++)
#pragma unroll
        for (int p = 0; p < 4; p++) acc[k][p] = 0ULL;

    const float* xb = x + (size_t)b * C_ * N_;

    for (int c0 = 0; c0 < C_; c0 += 32) {
        // load x tile [32 c][128 n], coalesced float4
#pragma unroll
        for (int r = 0; r < 4; r++) {
            int idx = t + r * 256;          // vec4 id, 0..1023
            int cc  = idx >> 5;
            int nn  = (idx & 31) * 4;
            *(float4*)&xs[cc][nn] =
                *(const float4*)&xb[(size_t)(c0 + cc) * N_ + n0 + nn];
        }
        // load W tile [64 o][32 c], scalar (padded smem)
#pragma unroll
        for (int r = 0; r < 8; r++) {
            int idx = t + r * 256;          // 0..2047
            int oo  = idx >> 5;
            int cc  = idx & 31;
            int og  = o0 + oo;
            const float* wrow = (og < 32) ? (wq + (size_t)og * C_)
                              : (og < 64) ? (wk + (size_t)(og - 32) * C_)
                                          : (wv + (size_t)(og - 64) * C_);
            ws[oo][cc] = wrow[c0 + cc];
        }
        __syncthreads();

#pragma unroll 8
        for (int cc = 0; cc < 32; cc++) {
            float4 a0 = *(float4*)&xs[cc][tyn * 8];
            float4 a1 = *(float4*)&xs[cc][tyn * 8 + 4];
            unsigned long long av[4] = { pack2(a0.x, a0.y), pack2(a0.z, a0.w),
                                         pack2(a1.x, a1.y), pack2(a1.z, a1.w) };
#pragma unroll
            for (int k = 0; k < 4; k++) {
                float w = ws[txo * 4 + k][cc];
                unsigned long long w2 = pack2(w, w);
#pragma unroll
                for (int p = 0; p < 4; p++) fma2(acc[k][p], w2, av[p]);
            }
        }
        __syncthreads();
    }

    // epilogue: bias + scatter to Q/K/V scratch
#pragma unroll
    for (int k = 0; k < 4; k++) {
        int og = o0 + txo * 4 + k;
        float bias;
        float* dst;
        int S, ol;
        if (og < 32)       { bias = bq[og];      dst = g_Q; S = CQ; ol = og; }
        else if (og < 64)  { bias = bk[og - 32]; dst = g_K; S = CQ; ol = og - 32; }
        else               { bias = bv[og - 64]; dst = g_V; S = C_; ol = og - 64; }
#pragma unroll
        for (int p = 0; p < 4; p++) {
            float2 v = unpack2(acc[k][p]);
            int n = n0 + tyn * 8 + p * 2;
            dst[((size_t)b * N_ + n    ) * S + ol] = v.x + bias;
            dst[((size_t)b * N_ + n + 1) * S + ol] = v.y + bias;
        }
    }
}

// ============================================================================
// Kernel 2: flash attention (no scale, softmax over keys) + residual
//   O[i][c] = sum_j softmax_j(Q[i]·K[j]) * V[j][c];  out = x + O^T
// grid: (N/128, C/128, B), block: 256, dyn smem 164864 B
// Thread map: tx = t&15, ti = t>>4.
//   Phase 1 (S):  rows i = ti*8..+8, keys j = tx + 16*jj (strided, bank-safe)
//   Phase 2 (PV): rows i = ti*8..+8, chans c = tx*8..+8 (f32x2 pairs along c)
// ============================================================================
#define BM 128
#define BN 128
#define BC 128

__global__ __launch_bounds__(256)
void attn_kernel(const float* __restrict__ x, float* __restrict__ out)
{
    extern __shared__ __align__(16) float sm[];
    float* sQ = sm;                       // [128][33]
    float* sK = sQ + 128 * 33;            // [128][33]
    float* sV = sK + 128 * 33;            // [128][128]  [j][c]
    float* sP = sV + 128 * 128;           // [128][128]  [i][j], later [c][i]

    const int b  = blockIdx.z;
    const int i0 = blockIdx.x * BM;
    const int c0 = blockIdx.y * BC;
    const int t  = threadIdx.x;
    const int tx = t & 15;
    const int ti = t >> 4;

    const float* Qg = g_Q + ((size_t)b * N_ + i0) * CQ;

    // load Q tile [128 i][32 d] -> sQ (padded rows)
#pragma unroll
    for (int r = 0; r < 4; r++) {
        int idx = t + r * 256;          // vec4 id
        int ii  = idx >> 3;
        int dd  = (idx & 7) * 4;
        float4 v = *(const float4*)&Qg[(size_t)ii * CQ + dd];
        float* d = &sQ[ii * 33 + dd];
        d[0] = v.x; d[1] = v.y; d[2] = v.z; d[3] = v.w;
    }

    float m[8], l[8];
    unsigned long long O2[8][4];
#pragma unroll
    for (int ii = 0; ii < 8; ii++) {
        m[ii] = -3.0e38f; l[ii] = 0.0f;
#pragma unroll
        for (int p = 0; p < 4; p++) O2[ii][p] = 0ULL;
    }

    for (int j0 = 0; j0 < N_; j0 += BN) {
        // ---- load K tile [128 j][32 d] and V tile [128 j][128 c] ----
        const float* Kg = g_K + ((size_t)b * N_ + j0) * CQ;
#pragma unroll
        for (int r = 0; r < 4; r++) {
            int idx = t + r * 256;
            int jj  = idx >> 3;
            int dd  = (idx & 7) * 4;
            float4 v = *(const float4*)&Kg[(size_t)jj * CQ + dd];
            float* d = &sK[jj * 33 + dd];
            d[0] = v.x; d[1] = v.y; d[2] = v.z; d[3] = v.w;
        }
#pragma unroll
        for (int r = 0; r < 16; r++) {
            int idx = t + r * 256;          // vec4 id, 0..4095
            int jj  = idx >> 5;
            int cc  = (idx & 31) * 4;
            *(float4*)&sV[jj * 128 + cc] =
                *(const float4*)&g_V[((size_t)b * N_ + j0 + jj) * C_ + c0 + cc];
        }
        __syncthreads();

        // ---- phase 1: S = Q K^T (8 i x 8 j per thread, scalar fp32) ----
        float s[8][8];
#pragma unroll
        for (int ii = 0; ii < 8; ii++)
#pragma unroll
            for (int jj = 0; jj < 8; jj++) s[ii][jj] = 0.0f;

#pragma unroll 8
        for (int d = 0; d < CQ; d++) {
            float q[8], k[8];
#pragma unroll
            for (int ii = 0; ii < 8; ii++) q[ii] = sQ[(ti * 8 + ii) * 33 + d];
#pragma unroll
            for (int jj = 0; jj < 8; jj++) k[jj] = sK[(tx + jj * 16) * 33 + d];
#pragma unroll
            for (int ii = 0; ii < 8; ii++)
#pragma unroll
                for (int jj = 0; jj < 8; jj++) s[ii][jj] += q[ii] * k[jj];
        }

        // ---- online softmax ----
        float f[8];
#pragma unroll
        for (int ii = 0; ii < 8; ii++) {
            float v = s[ii][0];
#pragma unroll
            for (int jj = 1; jj < 8; jj++) v = fmaxf(v, s[ii][jj]);
            v = red_max16(v);
            float mnew = fmaxf(m[ii], v);
            f[ii] = __expf(m[ii] - mnew);
            m[ii] = mnew;

            float rs = 0.0f;
#pragma unroll
            for (int jj = 0; jj < 8; jj++) {
                float p = __expf(s[ii][jj] - mnew);
                s[ii][jj] = p;
                rs += p;
            }
            rs = red_sum16(rs);
            l[ii] = l[ii] * f[ii] + rs;
        }
        // rescale O (f32x2)
#pragma unroll
        for (int ii = 0; ii < 8; ii++) {
            unsigned long long f2 = pack2(f[ii], f[ii]);
#pragma unroll
            for (int p = 0; p < 4; p++) O2[ii][p] = mul2(O2[ii][p], f2);
        }
        // write P -> sP[i][j]  (j = tx + 16*jj: conflict-free scalar stores)
#pragma unroll
        for (int ii = 0; ii < 8; ii++)
#pragma unroll
            for (int jj = 0; jj < 8; jj++)
                sP[(ti * 8 + ii) * 128 + tx + jj * 16] = s[ii][jj];
        __syncthreads();

        // ---- phase 2: O += P V  (f32x2 pairs along c) ----
#pragma unroll 2
        for (int j = 0; j < BN; j++) {
            float4 va = *(float4*)&sV[j * 128 + tx * 8];
            float4 vb = *(float4*)&sV[j * 128 + tx * 8 + 4];
            unsigned long long v2[4] = { pack2(va.x, va.y), pack2(va.z, va.w),
                                         pack2(vb.x, vb.y), pack2(vb.z, vb.w) };
#pragma unroll
            for (int ii = 0; ii < 8; ii++) {
                float p = sP[(ti * 8 + ii) * 128 + j];   // broadcast
                unsigned long long p2 = pack2(p, p);
                fma2(O2[ii][0], p2, v2[0]);
                fma2(O2[ii][1], p2, v2[1]);
                fma2(O2[ii][2], p2, v2[2]);
                fma2(O2[ii][3], p2, v2[3]);
            }
        }
        __syncthreads();
    }

    // ---- epilogue: normalize, transpose via smem, residual add, store ----
#pragma unroll
    for (int ii = 0; ii < 8; ii++) {
        float inv = 1.0f / l[ii];
#pragma unroll
        for (int p = 0; p < 4; p++) {
            float2 v = unpack2(O2[ii][p]);
            int cl = tx * 8 + p * 2;
            sP[(cl    ) * 128 + ti * 8 + ii] = v.x * inv;   // sO[c][i]
            sP[(cl + 1) * 128 + ti * 8 + ii] = v.y * inv;
        }
    }
    __syncthreads();

    const float* xb = x   + ((size_t)b * C_ + c0) * N_ + i0;
    float*       ob = out + ((size_t)b * C_ + c0) * N_ + i0;
#pragma unroll
    for (int r = 0; r < 16; r++) {
        int idx = t + r * 256;          // vec4 id, 0..4095
        int cc  = idx >> 5;
        int iv  = (idx & 31) * 4;
        float4 o4 = *(float4*)&sP[cc * 128 + iv];
        float4 xv = *(const float4*)&xb[(size_t)cc * N_ + iv];
        o4.x += xv.x; o4.y += xv.y; o4.z += xv.z; o4.w += xv.w;
        *(float4*)&ob[(size_t)cc * N_ + iv] = o4;
    }
}

// ============================================================================
extern "C" void kernel_launch(void* const* d_in, const int* in_sizes, int n_in,
                              void* d_out, int out_size)
{
    const float* x  = (const float*)d_in[0];
    const float* wq = (const float*)d_in[1];
    const float* bq = (const float*)d_in[2];
    const float* wk = (const float*)d_in[3];
    const float* bk = (const float*)d_in[4];
    const float* wv = (const float*)d_in[5];
    const float* bv = (const float*)d_in[6];
    float* out = (float*)d_out;

    // projections: Q,K -> [B,N,32]; V^T -> [B,N,256]
    proj_kernel<<<dim3(N_ / 128, 320 / 64, B_), 256>>>(x, wq, bq, wk, bk, wv, bv);

    // flash attention + residual
    const int smem = (2 * 128 * 33 + 2 * 128 * 128) * (int)sizeof(float); // 164864
    cudaFuncSetAttribute(attn_kernel,
                         cudaFuncAttributeMaxDynamicSharedMemorySize, smem);
    attn_kernel<<<dim3(N_ / BM, C_ / BC, B_), 256, smem>>>(x, out);
}

// round 10
// speedup vs baseline: 1.0010x; 1.0004x over previous
#include <cuda_runtime.h>
#include <math.h>
#include <stdint.h>

// Problem constants
#define B_   8
#define C_   256
#define N_   4096
#define CQ   32

// ---------------- scratch (static device arrays; no allocation) -------------
__device__ float g_Q[(size_t)B_ * N_ * CQ];   // [b][n][d]  4 MB
__device__ float g_K[(size_t)B_ * N_ * CQ];   // [b][n][d]  4 MB (K transposed)
__device__ float g_V[(size_t)B_ * N_ * C_];   // [b][n][c] 32 MB (V transposed)

// ---------------- f32x2 packed math helpers (sm_103a) -----------------------
__device__ __forceinline__ unsigned long long pack2(float x, float y) {
    unsigned long long r;
    asm("mov.b64 %0, {%1, %2};" : "=l"(r) : "f"(x), "f"(y));
    return r;
}
__device__ __forceinline__ float2 unpack2(unsigned long long v) {
    float2 r;
    asm("mov.b64 {%0, %1}, %2;" : "=f"(r.x), "=f"(r.y) : "l"(v));
    return r;
}
__device__ __forceinline__ void fma2(unsigned long long& d,
                                     unsigned long long a, unsigned long long b) {
    asm("fma.rn.f32x2 %0, %1, %2, %0;" : "+l"(d) : "l"(a), "l"(b));
}
__device__ __forceinline__ unsigned long long mul2(unsigned long long a,
                                                   unsigned long long b) {
    unsigned long long d;
    asm("mul.rn.f32x2 %0, %1, %2;" : "=l"(d) : "l"(a), "l"(b));
    return d;
}

// 16-lane (half-warp) reductions; tx = lane&15 threads share a row group
__device__ __forceinline__ float red_max16(float v) {
#pragma unroll
    for (int off = 8; off; off >>= 1)
        v = fmaxf(v, __shfl_xor_sync(0xffffffffu, v, off));
    return v;
}
__device__ __forceinline__ float red_sum16(float v) {
#pragma unroll
    for (int off = 8; off; off >>= 1)
        v += __shfl_xor_sync(0xffffffffu, v, off);
    return v;
}

// ============================================================================
// Kernel 1: fused Q/K/V projection (1x1 conv == channel GEMM)
//   out320[n][o] = sum_c x[b][c][n] * Wcat[o][c] + bcat[o]
//   o in [0,32)  -> Q[b][n][o]
//   o in [32,64) -> K[b][n][o-32]
//   o in [64,320)-> V[b][n][o-64]
// grid: (N/128, 320/64, B), block: 256
// ============================================================================
__global__ __launch_bounds__(256)
void proj_kernel(const float* __restrict__ x,
                 const float* __restrict__ wq, const float* __restrict__ bq,
                 const float* __restrict__ wk, const float* __restrict__ bk,
                 const float* __restrict__ wv, const float* __restrict__ bv)
{
    __shared__ __align__(16) float xs[32][128];   // [c][n] tile
    __shared__ float ws[64][33];                  // [o][c] tile, padded

    const int b  = blockIdx.z;
    const int n0 = blockIdx.x * 128;
    const int o0 = blockIdx.y * 64;
    const int t  = threadIdx.x;
    const int txo = t & 15;        // o group: 4 outputs each
    const int tyn = t >> 4;        // n group: 8 n each

    unsigned long long acc[4][4];  // [o][n-pair], f32x2 along n
#pragma unroll
    for (int k = 0; k < 4; k++)
#pragma unroll
        for (int p = 0; p < 4; p++) acc[k][p] = 0ULL;

    const float* xb = x + (size_t)b * C_ * N_;

    for (int c0 = 0; c0 < C_; c0 += 32) {
        // load x tile [32 c][128 n], coalesced float4
#pragma unroll
        for (int r = 0; r < 4; r++) {
            int idx = t + r * 256;          // vec4 id, 0..1023
            int cc  = idx >> 5;
            int nn  = (idx & 31) * 4;
            *(float4*)&xs[cc][nn] =
                *(const float4*)&xb[(size_t)(c0 + cc) * N_ + n0 + nn];
        }
        // load W tile [64 o][32 c], scalar (padded smem)
#pragma unroll
        for (int r = 0; r < 8; r++) {
            int idx = t + r * 256;          // 0..2047
            int oo  = idx >> 5;
            int cc  = idx & 31;
            int og  = o0 + oo;
            const float* wrow = (og < 32) ? (wq + (size_t)og * C_)
                              : (og < 64) ? (wk + (size_t)(og - 32) * C_)
                                          : (wv + (size_t)(og - 64) * C_);
            ws[oo][cc] = wrow[c0 + cc];
        }
        __syncthreads();

#pragma unroll 8
        for (int cc = 0; cc < 32; cc++) {
            float4 a0 = *(float4*)&xs[cc][tyn * 8];
            float4 a1 = *(float4*)&xs[cc][tyn * 8 + 4];
            unsigned long long av[4] = { pack2(a0.x, a0.y), pack2(a0.z, a0.w),
                                         pack2(a1.x, a1.y), pack2(a1.z, a1.w) };
#pragma unroll
            for (int k = 0; k < 4; k++) {
                float w = ws[txo * 4 + k][cc];
                unsigned long long w2 = pack2(w, w);
#pragma unroll
                for (int p = 0; p < 4; p++) fma2(acc[k][p], w2, av[p]);
            }
        }
        __syncthreads();
    }

    // epilogue: bias + scatter to Q/K/V scratch
#pragma unroll
    for (int k = 0; k < 4; k++) {
        int og = o0 + txo * 4 + k;
        float bias;
        float* dst;
        int S, ol;
        if (og < 32)       { bias = bq[og];      dst = g_Q; S = CQ; ol = og; }
        else if (og < 64)  { bias = bk[og - 32]; dst = g_K; S = CQ; ol = og - 32; }
        else               { bias = bv[og - 64]; dst = g_V; S = C_; ol = og - 64; }
#pragma unroll
        for (int p = 0; p < 4; p++) {
            float2 v = unpack2(acc[k][p]);
            int n = n0 + tyn * 8 + p * 2;
            dst[((size_t)b * N_ + n    ) * S + ol] = v.x + bias;
            dst[((size_t)b * N_ + n + 1) * S + ol] = v.y + bias;
        }
    }
}

// ============================================================================
// Kernel 2: flash attention (no scale, softmax over keys) + residual
//   O[i][c] = sum_j softmax_j(Q[i]·K[j]) * V[j][c];  out = x + O^T
// grid: (N/128, C/128, B), block: 256, dyn smem 164864 B
// Thread map: tx = t&15, ti = t>>4.
//   Phase 1 (S):  rows i = ti*8..+8, keys j = tx + 16*jj (strided, bank-safe)
//   Phase 2 (PV): rows i = ti*8..+8, chans c = tx*8..+8 (f32x2 pairs along c)
// ============================================================================
#define BM 128
#define BN 128
#define BC 128

__global__ __launch_bounds__(256)
void attn_kernel(const float* __restrict__ x, float* __restrict__ out)
{
    extern __shared__ __align__(16) float sm[];
    float* sQ = sm;                       // [128][33]
    float* sK = sQ + 128 * 33;            // [128][33]
    float* sV = sK + 128 * 33;            // [128][128]  [j][c]
    float* sP = sV + 128 * 128;           // [128][128]  [i][j], later [c][i]

    const int b  = blockIdx.z;
    const int i0 = blockIdx.x * BM;
    const int c0 = blockIdx.y * BC;
    const int t  = threadIdx.x;
    const int tx = t & 15;
    const int ti = t >> 4;

    const float* Qg = g_Q + ((size_t)b * N_ + i0) * CQ;

    // load Q tile [128 i][32 d] -> sQ (padded rows)
#pragma unroll
    for (int r = 0; r < 4; r++) {
        int idx = t + r * 256;          // vec4 id
        int ii  = idx >> 3;
        int dd  = (idx & 7) * 4;
        float4 v = *(const float4*)&Qg[(size_t)ii * CQ + dd];
        float* d = &sQ[ii * 33 + dd];
        d[0] = v.x; d[1] = v.y; d[2] = v.z; d[3] = v.w;
    }

    float m[8], l[8];
    unsigned long long O2[8][4];
#pragma unroll
    for (int ii = 0; ii < 8; ii++) {
        m[ii] = -3.0e38f; l[ii] = 0.0f;
#pragma unroll
        for (int p = 0; p < 4; p++) O2[ii][p] = 0ULL;
    }

    for (int j0 = 0; j0 < N_; j0 += BN) {
        // ---- load K tile [128 j][32 d] and V tile [128 j][128 c] ----
        const float* Kg = g_K + ((size_t)b * N_ + j0) * CQ;
#pragma unroll
        for (int r = 0; r < 4; r++) {
            int idx = t + r * 256;
            int jj  = idx >> 3;
            int dd  = (idx & 7) * 4;
            float4 v = *(const float4*)&Kg[(size_t)jj * CQ + dd];
            float* d = &sK[jj * 33 + dd];
            d[0] = v.x; d[1] = v.y; d[2] = v.z; d[3] = v.w;
        }
#pragma unroll
        for (int r = 0; r < 16; r++) {
            int idx = t + r * 256;          // vec4 id, 0..4095
            int jj  = idx >> 5;
            int cc  = (idx & 31) * 4;
            *(float4*)&sV[jj * 128 + cc] =
                *(const float4*)&g_V[((size_t)b * N_ + j0 + jj) * C_ + c0 + cc];
        }
        __syncthreads();

        // ---- phase 1: S = Q K^T (8 i x 8 j per thread, scalar fp32) ----
        float s[8][8];
#pragma unroll
        for (int ii = 0; ii < 8; ii++)
#pragma unroll
            for (int jj = 0; jj < 8; jj++) s[ii][jj] = 0.0f;

#pragma unroll 8
        for (int d = 0; d < CQ; d++) {
            float q[8], k[8];
#pragma unroll
            for (int ii = 0; ii < 8; ii++) q[ii] = sQ[(ti * 8 + ii) * 33 + d];
#pragma unroll
            for (int jj = 0; jj < 8; jj++) k[jj] = sK[(tx + jj * 16) * 33 + d];
#pragma unroll
            for (int ii = 0; ii < 8; ii++)
#pragma unroll
                for (int jj = 0; jj < 8; jj++) s[ii][jj] += q[ii] * k[jj];
        }

        // ---- online softmax ----
        float f[8];
#pragma unroll
        for (int ii = 0; ii < 8; ii++) {
            float v = s[ii][0];
#pragma unroll
            for (int jj = 1; jj < 8; jj++) v = fmaxf(v, s[ii][jj]);
            v = red_max16(v);
            float mnew = fmaxf(m[ii], v);
            f[ii] = __expf(m[ii] - mnew);
            m[ii] = mnew;

            float rs = 0.0f;
#pragma unroll
            for (int jj = 0; jj < 8; jj++) {
                float p = __expf(s[ii][jj] - mnew);
                s[ii][jj] = p;
                rs += p;
            }
            rs = red_sum16(rs);
            l[ii] = l[ii] * f[ii] + rs;
        }
        // rescale O (f32x2)
#pragma unroll
        for (int ii = 0; ii < 8; ii++) {
            unsigned long long f2 = pack2(f[ii], f[ii]);
#pragma unroll
            for (int p = 0; p < 4; p++) O2[ii][p] = mul2(O2[ii][p], f2);
        }
        // write P -> sP[i][j]  (j = tx + 16*jj: conflict-free scalar stores)
#pragma unroll
        for (int ii = 0; ii < 8; ii++)
#pragma unroll
            for (int jj = 0; jj < 8; jj++)
                sP[(ti * 8 + ii) * 128 + tx + jj * 16] = s[ii][jj];
        __syncthreads();

        // ---- phase 2: O += P V  (f32x2 pairs along c) ----
#pragma unroll 2
        for (int j = 0; j < BN; j++) {
            float4 va = *(float4*)&sV[j * 128 + tx * 8];
            float4 vb = *(float4*)&sV[j * 128 + tx * 8 + 4];
            unsigned long long v2[4] = { pack2(va.x, va.y), pack2(va.z, va.w),
                                         pack2(vb.x, vb.y), pack2(vb.z, vb.w) };
#pragma unroll
            for (int ii = 0; ii < 8; ii++) {
                float p = sP[(ti * 8 + ii) * 128 + j];   // broadcast
                unsigned long long p2 = pack2(p, p);
                fma2(O2[ii][0], p2, v2[0]);
                fma2(O2[ii][1], p2, v2[1]);
                fma2(O2[ii][2], p2, v2[2]);
                fma2(O2[ii][3], p2, v2[3]);
            }
        }
        __syncthreads();
    }

    // ---- epilogue: normalize, transpose via smem, residual add, store ----
#pragma unroll
    for (int ii = 0; ii < 8; ii++) {
        float inv = 1.0f / l[ii];
#pragma unroll
        for (int p = 0; p < 4; p++) {
            float2 v = unpack2(O2[ii][p]);
            int cl = tx * 8 + p * 2;
            sP[(cl    ) * 128 + ti * 8 + ii] = v.x * inv;   // sO[c][i]
            sP[(cl + 1) * 128 + ti * 8 + ii] = v.y * inv;
        }
    }
    __syncthreads();

    const float* xb = x   + ((size_t)b * C_ + c0) * N_ + i0;
    float*       ob = out + ((size_t)b * C_ + c0) * N_ + i0;
#pragma unroll
    for (int r = 0; r < 16; r++) {
        int idx = t + r * 256;          // vec4 id, 0..4095
        int cc  = idx >> 5;
        int iv  = (idx & 31) * 4;
        float4 o4 = *(float4*)&sP[cc * 128 + iv];
        float4 xv = *(const float4*)&xb[(size_t)cc * N_ + iv];
        o4.x += xv.x; o4.y += xv.y; o4.z += xv.z; o4.w += xv.w;
        *(float4*)&ob[(size_t)cc * N_ + iv] = o4;
    }
}

// ============================================================================
extern "C" void kernel_launch(void* const* d_in, const int* in_sizes, int n_in,
                              void* d_out, int out_size)
{
    const float* x  = (const float*)d_in[0];
    const float* wq = (const float*)d_in[1];
    const float* bq = (const float*)d_in[2];
    const float* wk = (const float*)d_in[3];
    const float* bk = (const float*)d_in[4];
    const float* wv = (const float*)d_in[5];
    const float* bv = (const float*)d_in[6];
    float* out = (float*)d_out;

    // projections: Q,K -> [B,N,32]; V^T -> [B,N,256]
    proj_kernel<<<dim3(N_ / 128, 320 / 64, B_), 256>>>(x, wq, bq, wk, bk, wv, bv);

    // flash attention + residual
    const int smem = (2 * 128 * 33 + 2 * 128 * 128) * (int)sizeof(float); // 164864
    cudaFuncSetAttribute(attn_kernel,
                         cudaFuncAttributeMaxDynamicSharedMemorySize, smem);
    attn_kernel<<<dim3(N_ / BM, C_ / BC, B_), 256, smem>>>(x, out);
}